// round 3
// baseline (speedup 1.0000x reference)
#include <cuda_runtime.h>
#include <cuda_fp16.h>
#include <cstdint>

#define IN_F 4096
#define OUT_F 4096
#define MAX_T 8192

#define BM 128
#define BN 128
#define BK 64
#define KSTRIDE (BK + 16)     // 80-byte smem row stride: conflict-free lane map
#define KT (IN_F / BK)        // 64 k-tiles

// Scratch (device globals: allocations are banned in kernel_launch)
__device__ __align__(16) int8_t g_qx[(size_t)MAX_T * IN_F];
__device__ __align__(16) int8_t g_qw[(size_t)OUT_F * IN_F];
__device__ float g_xs[MAX_T];
__device__ int g_x_is_f32;
__device__ int g_w_is_i32;

// ---------------------------------------------------------------------------
// Kernel 0: dtype detection (harness may promote fp16->fp32, int8->int32).
// Deterministic pure function of the inputs.
// ---------------------------------------------------------------------------
__global__ void detect_kernel(const void* xv, const void* wv) {
    if (threadIdx.x != 0 || blockIdx.x != 0) return;
    const float* xf = (const float*)xv;
    float mx = 0.f;
    for (int i = 0; i < 4096; i++) {
        float v = fabsf(xf[i]);
        if (v > mx) mx = v;
    }
    // true fp32 N(0,1): max ~4.  fp16-pair misread as fp32: >8 w.p. ~1.
    g_x_is_f32 = (mx < 8.0f) ? 1 : 0;

    const int* wi = (const int*)wv;
    int ok = 1;
    for (int i = 0; i < 256; i++) {
        int v = wi[i];
        if (v < -128 || v > 127) ok = 0;
    }
    g_w_is_i32 = ok;   // packed int8 bytes essentially never sign-extend
}

// ---------------------------------------------------------------------------
// Kernel 1: weight repack int32 -> int8 (no-op if weight already int8).
// ---------------------------------------------------------------------------
__global__ void repack_w_kernel(const void* wv) {
    if (!g_w_is_i32) return;
    size_t idx = (size_t)blockIdx.x * blockDim.x + threadIdx.x;  // one per 4 elems
    const int4* w4 = (const int4*)wv;
    int4 v = w4[idx];
    char4 c;
    c.x = (char)v.x; c.y = (char)v.y; c.z = (char)v.z; c.w = (char)v.w;
    reinterpret_cast<char4*>(g_qw)[idx] = c;
}

// ---------------------------------------------------------------------------
// Kernel 2: per-token dynamic quantization. One 256-thread CTA per token.
// scale = max|x|/127 (fp32); q = round(x/scale) clipped, matching reference.
// ---------------------------------------------------------------------------
__global__ void quant_kernel(const void* xv, int T) {
    int t = blockIdx.x;
    if (t >= T) return;
    int tid = threadIdx.x;

    float vals[16];   // columns [tid*16, tid*16+16)
    if (g_x_is_f32) {
        const float4* row = reinterpret_cast<const float4*>(
            (const float*)xv + (size_t)t * IN_F);
#pragma unroll
        for (int i = 0; i < 4; i++) {
            float4 v = row[tid * 4 + i];
            vals[4 * i + 0] = v.x; vals[4 * i + 1] = v.y;
            vals[4 * i + 2] = v.z; vals[4 * i + 3] = v.w;
        }
    } else {
        const float4* row = reinterpret_cast<const float4*>(
            (const __half*)xv + (size_t)t * IN_F);
        float4 v0 = row[tid * 2 + 0];
        float4 v1 = row[tid * 2 + 1];
        const __half2* h0 = reinterpret_cast<const __half2*>(&v0);
        const __half2* h1 = reinterpret_cast<const __half2*>(&v1);
#pragma unroll
        for (int i = 0; i < 4; i++) {
            float2 f = __half22float2(h0[i]);
            vals[2 * i] = f.x; vals[2 * i + 1] = f.y;
        }
#pragma unroll
        for (int i = 0; i < 4; i++) {
            float2 f = __half22float2(h1[i]);
            vals[8 + 2 * i] = f.x; vals[8 + 2 * i + 1] = f.y;
        }
    }

    float m = 0.f;
#pragma unroll
    for (int i = 0; i < 16; i++) m = fmaxf(m, fabsf(vals[i]));
#pragma unroll
    for (int o = 16; o > 0; o >>= 1)
        m = fmaxf(m, __shfl_xor_sync(0xffffffffu, m, o));

    __shared__ float sm[8];
    int lane = tid & 31, wid = tid >> 5;
    if (lane == 0) sm[wid] = m;
    __syncthreads();
    if (tid < 8) {
        float v = sm[tid];
#pragma unroll
        for (int o = 4; o > 0; o >>= 1)
            v = fmaxf(v, __shfl_xor_sync(0xffu, v, o));
        if (tid == 0) sm[0] = v;
    }
    __syncthreads();
    float scale = sm[0] / 127.0f;
    if (tid == 0) g_xs[t] = scale;

    int8_t q[16];
#pragma unroll
    for (int i = 0; i < 16; i++) {
        float r = rintf(__fdiv_rn(vals[i], scale));
        r = fminf(fmaxf(r, -128.f), 127.f);
        q[i] = (int8_t)(int)r;
    }
    *reinterpret_cast<int4*>(g_qx + (size_t)t * IN_F + tid * 16) =
        *reinterpret_cast<const int4*>(q);
}

// ---------------------------------------------------------------------------
// Kernel 3: int8 GEMM (q_x [T,K] @ W[N,K]^T) via mma.m16n8k32.s8, direct LDS
// fragment loads at PTX-spec lane coords (conflict-free with KSTRIDE=80).
// 8 warps: 4(M) x 2(N); warp tile 32x64; per-warp mma grid 2x8.
// Fused dequant + fp16-rounded bias epilogue; output fp32 or fp16 per flag.
// ---------------------------------------------------------------------------
__device__ __forceinline__ void cp16(uint32_t dst, const void* src) {
    asm volatile("cp.async.cg.shared.global [%0], [%1], 16;\n" ::"r"(dst), "l"(src));
}

__global__ void __launch_bounds__(256, 2)
gemm_kernel(const void* Worig, const void* wscv, const void* biasv,
            void* Yv, int T) {
    __shared__ __align__(128) int8_t sA[2][BM * KSTRIDE];
    __shared__ __align__(128) int8_t sB[2][BN * KSTRIDE];

    int tid = threadIdx.x;
    int m0 = blockIdx.y * BM;
    int n0 = blockIdx.x * BN;

    const int8_t* W = g_w_is_i32 ? g_qw : (const int8_t*)Worig;

    auto load_tile = [&](int stage, int k0) {
        uint32_t abase = (uint32_t)__cvta_generic_to_shared(sA[stage]);
        uint32_t bbase = (uint32_t)__cvta_generic_to_shared(sB[stage]);
#pragma unroll
        for (int i = 0; i < 2; i++) {
            int c = tid + i * 256;
            int r = c >> 2, p = (c & 3) * 16;
            cp16(abase + r * KSTRIDE + p,
                 g_qx + (size_t)(m0 + r) * IN_F + k0 + p);
            cp16(bbase + r * KSTRIDE + p,
                 W + (size_t)(n0 + r) * IN_F + k0 + p);
        }
    };

    int lane = tid & 31;
    int warp = tid >> 5;
    int wm = (warp & 3) * 32;
    int wn = (warp >> 2) * 64;
    int quad = lane >> 2;        // fragment row/col group
    int four = (lane & 3) * 4;   // k byte offset

    int c[2][8][4];
#pragma unroll
    for (int mt = 0; mt < 2; mt++)
#pragma unroll
        for (int nt = 0; nt < 8; nt++)
#pragma unroll
            for (int i = 0; i < 4; i++) c[mt][nt][i] = 0;

    load_tile(0, 0);
    asm volatile("cp.async.commit_group;\n");

    for (int kt = 0; kt < KT; ++kt) {
        if (kt + 1 < KT) {
            load_tile((kt + 1) & 1, (kt + 1) * BK);
            asm volatile("cp.async.commit_group;\n");
            asm volatile("cp.async.wait_group 1;\n");
        } else {
            asm volatile("cp.async.wait_group 0;\n");
        }
        __syncthreads();

        int st = kt & 1;
        const int8_t* pA = sA[st];
        const int8_t* pB = sB[st];

#pragma unroll
        for (int kk = 0; kk < BK; kk += 32) {
            int a[2][4];
#pragma unroll
            for (int mt = 0; mt < 2; ++mt) {
                const int8_t* base = pA + (wm + mt * 16 + quad) * KSTRIDE + kk + four;
                a[mt][0] = *reinterpret_cast<const int*>(base);
                a[mt][1] = *reinterpret_cast<const int*>(base + 8 * KSTRIDE);
                a[mt][2] = *reinterpret_cast<const int*>(base + 16);
                a[mt][3] = *reinterpret_cast<const int*>(base + 8 * KSTRIDE + 16);
            }
            int b[8][2];
#pragma unroll
            for (int nt = 0; nt < 8; ++nt) {
                const int8_t* base = pB + (wn + nt * 8 + quad) * KSTRIDE + kk + four;
                b[nt][0] = *reinterpret_cast<const int*>(base);
                b[nt][1] = *reinterpret_cast<const int*>(base + 16);
            }
#pragma unroll
            for (int mt = 0; mt < 2; ++mt)
#pragma unroll
                for (int nt = 0; nt < 8; ++nt)
                    asm volatile(
                        "mma.sync.aligned.m16n8k32.row.col.s32.s8.s8.s32 "
                        "{%0,%1,%2,%3},{%4,%5,%6,%7},{%8,%9},{%0,%1,%2,%3};\n"
                        : "+r"(c[mt][nt][0]), "+r"(c[mt][nt][1]),
                          "+r"(c[mt][nt][2]), "+r"(c[mt][nt][3])
                        : "r"(a[mt][0]), "r"(a[mt][1]), "r"(a[mt][2]), "r"(a[mt][3]),
                          "r"(b[nt][0]), "r"(b[nt][1]));
        }
        __syncthreads();
    }

    // Epilogue: y = fp16(q * ws[n] * xs[m]); y += bias[n] in fp16 (as reference)
    bool f32io = (g_x_is_f32 != 0);
#pragma unroll
    for (int mt = 0; mt < 2; ++mt) {
        int r0 = m0 + wm + mt * 16 + quad;
        float xs0 = g_xs[r0];
        float xs1 = g_xs[r0 + 8];
#pragma unroll
        for (int nt = 0; nt < 8; ++nt) {
            int cg = n0 + wn + nt * 8 + (lane & 3) * 2;
            float w0, w1;
            __half b0, b1;
            if (f32io) {
                w0 = ((const float*)wscv)[cg];
                w1 = ((const float*)wscv)[cg + 1];
                b0 = __float2half(((const float*)biasv)[cg]);      // exact (orig fp16)
                b1 = __float2half(((const float*)biasv)[cg + 1]);
            } else {
                w0 = __half2float(((const __half*)wscv)[cg]);
                w1 = __half2float(((const __half*)wscv)[cg + 1]);
                b0 = ((const __half*)biasv)[cg];
                b1 = ((const __half*)biasv)[cg + 1];
            }
            __half y00 = __hadd(__float2half((float)c[mt][nt][0] * w0 * xs0), b0);
            __half y01 = __hadd(__float2half((float)c[mt][nt][1] * w1 * xs0), b1);
            __half y10 = __hadd(__float2half((float)c[mt][nt][2] * w0 * xs1), b0);
            __half y11 = __hadd(__float2half((float)c[mt][nt][3] * w1 * xs1), b1);
            if (f32io) {
                float* Y = (float*)Yv;
                float2 o0 = make_float2(__half2float(y00), __half2float(y01));
                float2 o1 = make_float2(__half2float(y10), __half2float(y11));
                *reinterpret_cast<float2*>(Y + (size_t)r0 * OUT_F + cg) = o0;
                *reinterpret_cast<float2*>(Y + (size_t)(r0 + 8) * OUT_F + cg) = o1;
            } else {
                __half* Y = (__half*)Yv;
                __half2 o0, o1;
                o0.x = y00; o0.y = y01;
                o1.x = y10; o1.y = y11;
                *reinterpret_cast<__half2*>(Y + (size_t)r0 * OUT_F + cg) = o0;
                *reinterpret_cast<__half2*>(Y + (size_t)(r0 + 8) * OUT_F + cg) = o1;
            }
        }
    }
}

// ---------------------------------------------------------------------------
extern "C" void kernel_launch(void* const* d_in, const int* in_sizes, int n_in,
                              void* d_out, int out_size) {
    const void* x    = d_in[0];
    const void* w    = d_in[1];
    const void* wsc  = d_in[2];
    const void* bias = d_in[3];
    int T = in_sizes[0] / IN_F;

    detect_kernel<<<1, 32>>>(x, w);
    repack_w_kernel<<<(OUT_F * IN_F / 4) / 256, 256>>>(w);
    quant_kernel<<<T, 256>>>(x, T);

    dim3 grid(OUT_F / BN, (T + BM - 1) / BM);
    gemm_kernel<<<grid, 256>>>(w, wsc, bias, d_out, T);
}